// round 15
// baseline (speedup 1.0000x reference)
#include <cuda_runtime.h>
#include <cuda_bf16.h>
#include <cstdint>

#define N_NODES 100000
#define N_EDGES 1600000
#define IN_CH   768
#define HID_CH  256
#define OUT_CH  2

#define SCAN_B 1024
#define N_SCAN_BLKS ((N_NODES + SCAN_B - 1) / SCAN_B)   // 98

// ---- scratch (device globals; allocation is forbidden) ----
__device__ __align__(16) float g_xw[(size_t)N_NODES * HID_CH]; // x @ W1
__device__ float g_deg [N_NODES];
__device__ float g_dinv[N_NODES];
__device__ __align__(8) float g_hw[(size_t)N_NODES * OUT_CH];  // relu(h) @ W2
__device__ int   g_cnt[N_NODES];
__device__ int   g_off[N_NODES];
__device__ int   g_cursor[N_NODES];
__device__ int   g_bsum[N_SCAN_BLKS];
__device__ int   g_csr_src[N_EDGES];
__device__ float g_csr_nrm[N_EDGES];
__device__ int   g_is64;
// W1 split to bf16 hi/lo, SAME [K][N] layout as input (for cp.async B tiles)
__device__ __align__(16) __nv_bfloat16 g_w1h[(size_t)IN_CH * HID_CH];
__device__ __align__(16) __nv_bfloat16 g_w1l[(size_t)IN_CH * HID_CH];

#define INIT_BLKS  ((N_NODES + 255) / 256)             // 391
#define SPLIT_BLKS ((IN_CH * HID_CH + 255) / 256)      // 768
#define SETUP_BLKS (INIT_BLKS + SPLIT_BLKS + 1)

// ---- fused setup: init deg/cnt, split W1, detect edge dtype ----
__global__ void k_setup(const float* __restrict__ W1,
                        const unsigned long long* __restrict__ ei) {
    int b = blockIdx.x;
    int tid = threadIdx.x;
    if (b < INIT_BLKS) {
        int i = b * 256 + tid;
        if (i < N_NODES) { g_deg[i] = 1.0f; g_cnt[i] = 0; }
    } else if (b < INIT_BLKS + SPLIT_BLKS) {
        int idx = (b - INIT_BLKS) * 256 + tid;
        if (idx < IN_CH * HID_CH) {
            float v = W1[idx];
            __nv_bfloat16 h = __float2bfloat16(v);
            __nv_bfloat16 l = __float2bfloat16(v - __bfloat162float(h));
            g_w1h[idx] = h;
            g_w1l[idx] = l;
        }
    } else {
        if (tid < 32) {
            bool hi = false;
            for (int i = tid; i < 1024; i += 32)
                hi |= (ei[i] >> 32) != 0ull;
            unsigned m = __ballot_sync(0xffffffffu, hi);
            if (tid == 0) g_is64 = (m == 0u);
        }
    }
}

__device__ __forceinline__ void load_edge(const void* ei_raw, int e, int& s, int& d) {
    if (g_is64) {
        const long long* ei = (const long long*)ei_raw;
        s = (int)ei[e];
        d = (int)ei[N_EDGES + e];
    } else {
        const int* ei = (const int*)ei_raw;
        s = ei[e];
        d = ei[N_EDGES + e];
    }
    if ((unsigned)s >= N_NODES) s = 0;
    if ((unsigned)d >= N_NODES) d = 0;
}

__global__ void k_prep(const void* __restrict__ ei_raw, const float* __restrict__ ew) {
    int e = blockIdx.x * blockDim.x + threadIdx.x;
    if (e >= N_EDGES) return;
    int s, d;
    load_edge(ei_raw, e, s, d);
    atomicAdd(&g_deg[d], ew[e]);
    atomicAdd(&g_cnt[d], 1);
}

// ---- scan1 with fused dinv (deg is final after k_prep) ----
__global__ void k_scan1() {
    __shared__ int s[SCAN_B];
    int tid = threadIdx.x;
    int i = blockIdx.x * SCAN_B + tid;
    if (i < N_NODES) {
        float dg = g_deg[i];
        g_dinv[i] = dg > 0.f ? rsqrtf(dg) : 0.f;
    }
    int v = (i < N_NODES) ? g_cnt[i] : 0;
    s[tid] = v;
    __syncthreads();
    #pragma unroll
    for (int d = 1; d < SCAN_B; d <<= 1) {
        int t = (tid >= d) ? s[tid - d] : 0;
        __syncthreads();
        s[tid] += t;
        __syncthreads();
    }
    if (i < N_NODES) g_off[i] = s[tid] - v;
    if (tid == SCAN_B - 1) g_bsum[blockIdx.x] = s[tid];
}

__global__ void k_scan2() {
    __shared__ int s[128];
    int tid = threadIdx.x;
    int v = (tid < N_SCAN_BLKS) ? g_bsum[tid] : 0;
    s[tid] = v;
    __syncthreads();
    #pragma unroll
    for (int d = 1; d < 128; d <<= 1) {
        int t = (tid >= d) ? s[tid - d] : 0;
        __syncthreads();
        s[tid] += t;
        __syncthreads();
    }
    if (tid < N_SCAN_BLKS) g_bsum[tid] = s[tid] - v;
}

__global__ void k_scan3() {
    int i = blockIdx.x * blockDim.x + threadIdx.x;
    if (i < N_NODES) {
        int o = g_off[i] + g_bsum[i / SCAN_B];
        g_off[i] = o;
        g_cursor[i] = o;
    }
}

__global__ void k_scatter(const void* __restrict__ ei_raw, const float* __restrict__ ew) {
    int e = blockIdx.x * blockDim.x + threadIdx.x;
    if (e >= N_EDGES) return;
    int s, d;
    load_edge(ei_raw, e, s, d);
    int pos = atomicAdd(&g_cursor[d], 1);
    if ((unsigned)pos >= N_EDGES) return;
    g_csr_src[pos] = s;
    g_csr_nrm[pos] = g_dinv[s] * ew[e] * g_dinv[d];
}

// == HMMA GEMM1 bf16-split 3-pass: BM=64 x BN=256, 256 thr, 2 CTAs/SM ======
__device__ __forceinline__ uint32_t smem_u32(const void* p) {
    return (uint32_t)__cvta_generic_to_shared(p);
}
__device__ __forceinline__ void ldsm_x4(uint32_t* r, uint32_t addr) {
    asm volatile("ldmatrix.sync.aligned.m8n8.x4.shared.b16 {%0,%1,%2,%3}, [%4];"
        : "=r"(r[0]), "=r"(r[1]), "=r"(r[2]), "=r"(r[3]) : "r"(addr));
}
__device__ __forceinline__ void ldsm_x4t(uint32_t* r, uint32_t addr) {
    asm volatile("ldmatrix.sync.aligned.m8n8.x4.trans.shared.b16 {%0,%1,%2,%3}, [%4];"
        : "=r"(r[0]), "=r"(r[1]), "=r"(r[2]), "=r"(r[3]) : "r"(addr));
}
__device__ __forceinline__ void mma_bf16(float* c, const uint32_t* a, const uint32_t* b) {
    asm volatile("mma.sync.aligned.m16n8k16.row.col.f32.bf16.bf16.f32 "
        "{%0,%1,%2,%3}, {%4,%5,%6,%7}, {%8,%9}, {%0,%1,%2,%3};"
        : "+f"(c[0]), "+f"(c[1]), "+f"(c[2]), "+f"(c[3])
        : "r"(a[0]), "r"(a[1]), "r"(a[2]), "r"(a[3]), "r"(b[0]), "r"(b[1]));
}
__device__ __forceinline__ uint32_t pack_split(float a, float b, uint32_t& lo) {
    __nv_bfloat16 ha = __float2bfloat16(a);
    __nv_bfloat16 hb = __float2bfloat16(b);
    __nv_bfloat16 la = __float2bfloat16(a - __bfloat162float(ha));
    __nv_bfloat16 lb = __float2bfloat16(b - __bfloat162float(hb));
    __nv_bfloat162 l2(la, lb); lo = *(uint32_t*)&l2;
    __nv_bfloat162 h2(ha, hb); return *(uint32_t*)&h2;
}
#define CP_ASYNC16(dst, src) \
    asm volatile("cp.async.cg.shared.global [%0], [%1], 16;" :: "r"(dst), "l"(src))
#define CP_COMMIT() asm volatile("cp.async.commit_group;" ::: "memory")
#define CP_WAIT0()  asm volatile("cp.async.wait_group 0;" ::: "memory")

#define BM 64
#define BN 256
#define BK 32
#define A_PITCH 40
#define B_PITCH 264
#define A_ST (BM * A_PITCH)   // 2560 halves
#define B_ST (BK * B_PITCH)   // 8448 halves
#define GEMM_SMEM_BYTES ((4 * A_ST + 4 * B_ST) * 2)   // 88064

__global__ __launch_bounds__(256, 2)
void k_gemm1_tc(const float* __restrict__ A) {
    extern __shared__ __align__(16) __nv_bfloat16 sm[];
    __nv_bfloat16* AH = sm;                 // [2][BM][A_PITCH]
    __nv_bfloat16* AL = AH + 2 * A_ST;
    __nv_bfloat16* BH = AL + 2 * A_ST;      // [2][BK][B_PITCH]
    __nv_bfloat16* BL = BH + 2 * B_ST;

    const int tid  = threadIdx.x;
    const int lane = tid & 31;
    const int wid  = tid >> 5;
    const int warp_m = wid & 1;             // 2 groups x 32 rows
    const int warp_n = wid >> 1;            // 4 groups x 64 cols
    const int m0 = blockIdx.x * BM;

    const int ar = tid >> 2;                // 0..63
    const int ac = (tid & 3) * 8;           // 0,8,16,24
    const bool a_ok = (m0 + ar) < N_NODES;

    float4 ra[2];
    #define LOAD_A(k0)                                                           \
        do {                                                                     \
            if (a_ok) {                                                          \
                const float* ap = A + (size_t)(m0 + ar) * IN_CH + (k0) + ac;     \
                ra[0] = *(const float4*)(ap);                                    \
                ra[1] = *(const float4*)(ap + 4);                                \
            } else {                                                             \
                ra[0] = ra[1] = make_float4(0.f, 0.f, 0.f, 0.f);                 \
            }                                                                    \
        } while (0)

    #define STS_A(st)                                                            \
        do {                                                                     \
            uint32_t h0, h1, h2, h3, l0, l1, l2, l3;                             \
            h0 = pack_split(ra[0].x, ra[0].y, l0);                               \
            h1 = pack_split(ra[0].z, ra[0].w, l1);                               \
            h2 = pack_split(ra[1].x, ra[1].y, l2);                               \
            h3 = pack_split(ra[1].z, ra[1].w, l3);                               \
            uint32_t off = ar * A_PITCH + ac;                                    \
            *(uint4*)(AH + (st) * A_ST + off) = make_uint4(h0, h1, h2, h3);      \
            *(uint4*)(AL + (st) * A_ST + off) = make_uint4(l0, l1, l2, l3);      \
        } while (0)

    // B: 32 rows x 32 segs (8 halves each) = 1024 segs per buffer; 256 thr x4
    #define CP_B(k0, st)                                                         \
        do {                                                                     \
            _Pragma("unroll")                                                    \
            for (int j = 0; j < 4; j++) {                                        \
                int u = tid + j * 256;                                           \
                int rw = u >> 5, sg = (u & 31) * 8;                              \
                uint32_t doff = ((st) * B_ST + rw * B_PITCH + sg) * 2;           \
                const __nv_bfloat16* sh = g_w1h + (size_t)((k0) + rw) * HID_CH + sg; \
                const __nv_bfloat16* sl = g_w1l + (size_t)((k0) + rw) * HID_CH + sg; \
                CP_ASYNC16(smem_u32(BH) + doff, sh);                             \
                CP_ASYNC16(smem_u32(BL) + doff, sl);                             \
            }                                                                    \
        } while (0)

    float acc[2][8][4];
    #pragma unroll
    for (int mi = 0; mi < 2; mi++)
        #pragma unroll
        for (int ni = 0; ni < 8; ni++)
            #pragma unroll
            for (int q = 0; q < 4; q++) acc[mi][ni][q] = 0.f;

    LOAD_A(0);
    CP_B(0, 0);
    CP_COMMIT();
    STS_A(0);
    CP_WAIT0();
    __syncthreads();

    const int bg   = lane >> 3;
    const int brow = ((bg & 1) << 3) + (lane & 7);
    const int bcol = (bg >> 1) << 3;

    int stage = 0;
    for (int k0 = 0; k0 < IN_CH; k0 += BK) {
        const bool has_next = (k0 + BK) < IN_CH;
        if (has_next) {
            LOAD_A(k0 + BK);
            CP_B(k0 + BK, stage ^ 1);
            CP_COMMIT();
        }

        const __nv_bfloat16* AHs = AH + stage * A_ST;
        const __nv_bfloat16* ALs = AL + stage * A_ST;
        const __nv_bfloat16* BHs = BH + stage * B_ST;
        const __nv_bfloat16* BLs = BL + stage * B_ST;

        #pragma unroll
        for (int ks = 0; ks < 2; ks++) {
            const int kk = ks * 16;
            uint32_t ah[2][4], al[2][4];
            {
                int row = warp_m * 32 + (lane & 15);
                int col = kk + ((lane >> 4) << 3);
                #pragma unroll
                for (int mi = 0; mi < 2; mi++) {
                    ldsm_x4(ah[mi], smem_u32(AHs + (row + mi * 16) * A_PITCH + col));
                    ldsm_x4(al[mi], smem_u32(ALs + (row + mi * 16) * A_PITCH + col));
                }
            }
            #pragma unroll
            for (int ni = 0; ni < 8; ni += 2) {
                int n = warp_n * 64 + ni * 8 + bcol;
                uint32_t bh[4], bl[4];
                ldsm_x4t(bh, smem_u32(BHs + (kk + brow) * B_PITCH + n));
                ldsm_x4t(bl, smem_u32(BLs + (kk + brow) * B_PITCH + n));
                #pragma unroll
                for (int mi = 0; mi < 2; mi++) {
                    mma_bf16(acc[mi][ni],     ah[mi], bh);
                    mma_bf16(acc[mi][ni],     ah[mi], bl);
                    mma_bf16(acc[mi][ni],     al[mi], bh);
                    mma_bf16(acc[mi][ni + 1], ah[mi], bh + 2);
                    mma_bf16(acc[mi][ni + 1], ah[mi], bl + 2);
                    mma_bf16(acc[mi][ni + 1], al[mi], bh + 2);
                }
            }
        }
        if (has_next) {
            STS_A(stage ^ 1);
            CP_WAIT0();
        }
        __syncthreads();
        stage ^= 1;
    }

    #pragma unroll
    for (int mi = 0; mi < 2; mi++) {
        int r = m0 + warp_m * 32 + mi * 16 + (lane >> 2);
        int cb = warp_n * 64 + (lane & 3) * 2;
        #pragma unroll
        for (int ni = 0; ni < 8; ni++) {
            int c = cb + ni * 8;
            if (r < N_NODES)
                *(float2*)(g_xw + (size_t)r * HID_CH + c) =
                    make_float2(acc[mi][ni][0], acc[mi][ni][1]);
            if (r + 8 < N_NODES)
                *(float2*)(g_xw + (size_t)(r + 8) * HID_CH + c) =
                    make_float2(acc[mi][ni][2], acc[mi][ni][3]);
        }
    }
}

// ---- fused layer-1 aggregation + bias + ReLU + GEMM2 (256 -> 2) ----
// One warp per node, lane owns 8 contiguous channels (R9 structure).
__global__ __launch_bounds__(256)
void k_agg_fused(const float* __restrict__ b1, const float* __restrict__ W2) {
    __shared__ float sW2[HID_CH * OUT_CH];
    __shared__ float sb1[HID_CH];
    int tid = threadIdx.x;
    sW2[tid] = W2[tid];
    sW2[tid + 256] = W2[tid + 256];
    sb1[tid] = b1[tid];
    __syncthreads();

    int node = (blockIdx.x * blockDim.x + tid) >> 5;
    int lane = tid & 31;
    if (node >= N_NODES) return;

    float di = g_dinv[node];
    float self = di * di;
    const float4* nrow = (const float4*)(g_xw + (size_t)node * HID_CH) + lane * 2;
    float4 v0 = nrow[0], v1 = nrow[1];
    float4 acc0 = make_float4(self * v0.x, self * v0.y, self * v0.z, self * v0.w);
    float4 acc1 = make_float4(self * v1.x, self * v1.y, self * v1.z, self * v1.w);

    int begin = g_off[node];
    int end = begin + g_cnt[node];
    for (int j0 = begin; j0 < end; j0 += 32) {
        int m = end - j0; if (m > 32) m = 32;
        int   s_l = (lane < m) ? g_csr_src[j0 + lane] : 0;
        float w_l = (lane < m) ? g_csr_nrm[j0 + lane] : 0.f;
        for (int t = 0; t < m; t++) {
            int   s = __shfl_sync(0xffffffffu, s_l, t);
            float w = __shfl_sync(0xffffffffu, w_l, t);
            const float4* r = (const float4*)(g_xw + (size_t)s * HID_CH) + lane * 2;
            float4 u0 = __ldg(r);
            float4 u1 = __ldg(r + 1);
            acc0.x += w * u0.x; acc0.y += w * u0.y; acc0.z += w * u0.z; acc0.w += w * u0.w;
            acc1.x += w * u1.x; acc1.y += w * u1.y; acc1.z += w * u1.z; acc1.w += w * u1.w;
        }
    }

    int c = lane * 8;
    float h[8];
    h[0] = fmaxf(acc0.x + sb1[c + 0], 0.f);
    h[1] = fmaxf(acc0.y + sb1[c + 1], 0.f);
    h[2] = fmaxf(acc0.z + sb1[c + 2], 0.f);
    h[3] = fmaxf(acc0.w + sb1[c + 3], 0.f);
    h[4] = fmaxf(acc1.x + sb1[c + 4], 0.f);
    h[5] = fmaxf(acc1.y + sb1[c + 5], 0.f);
    h[6] = fmaxf(acc1.z + sb1[c + 6], 0.f);
    h[7] = fmaxf(acc1.w + sb1[c + 7], 0.f);
    float a0 = 0.f, a1 = 0.f;
    #pragma unroll
    for (int i = 0; i < 8; i++) {
        a0 += h[i] * sW2[(c + i) * 2];
        a1 += h[i] * sW2[(c + i) * 2 + 1];
    }
    #pragma unroll
    for (int off = 16; off > 0; off >>= 1) {
        a0 += __shfl_down_sync(0xffffffffu, a0, off);
        a1 += __shfl_down_sync(0xffffffffu, a1, off);
    }
    if (lane == 0) {
        g_hw[node * 2]     = a0;
        g_hw[node * 2 + 1] = a1;
    }
}

// ---- layer-2 aggregation via CSR ----
__global__ void k_out2(const float* __restrict__ b2, float* __restrict__ out) {
    int n = blockIdx.x * blockDim.x + threadIdx.x;
    if (n >= N_NODES) return;
    float di = g_dinv[n];
    float self = di * di;
    float a0 = g_hw[2 * n]     * self;
    float a1 = g_hw[2 * n + 1] * self;
    int begin = g_off[n];
    int end = begin + g_cnt[n];
    for (int j = begin; j < end; j++) {
        int   s = g_csr_src[j];
        float w = g_csr_nrm[j];
        a0 += w * g_hw[2 * s];
        a1 += w * g_hw[2 * s + 1];
    }
    out[2 * n]     = a0 + b2[0];
    out[2 * n + 1] = a1 + b2[1];
}

extern "C" void kernel_launch(void* const* d_in, const int* in_sizes, int n_in,
                              void* d_out, int out_size) {
    const float* x  = (const float*)d_in[0];
    const void*  ei = d_in[1];
    const float* ew = (const float*)d_in[2];
    const float* W1 = (const float*)d_in[3];
    const float* b1 = (const float*)d_in[4];
    const float* W2 = (const float*)d_in[5];
    const float* b2 = (const float*)d_in[6];
    float* out = (float*)d_out;

    const int NODE_BLKS = (N_NODES + 255) / 256;
    const int EDGE_BLKS = (N_EDGES + 255) / 256;

    cudaFuncSetAttribute(k_gemm1_tc,
                         cudaFuncAttributeMaxDynamicSharedMemorySize, GEMM_SMEM_BYTES);

    // Serial single stream.
    k_setup<<<SETUP_BLKS, 256>>>(W1, (const unsigned long long*)ei);

    k_gemm1_tc<<<(N_NODES + BM - 1) / BM, 256, GEMM_SMEM_BYTES>>>(x);

    k_prep<<<EDGE_BLKS, 256>>>(ei, ew);
    k_scan1<<<N_SCAN_BLKS, SCAN_B>>>();     // dinv fused here
    k_scan2<<<1, 128>>>();
    k_scan3<<<NODE_BLKS, 256>>>();
    k_scatter<<<EDGE_BLKS, 256>>>(ei, ew);

    k_agg_fused<<<(N_NODES * 32 + 255) / 256, 256>>>(b1, W2);

    k_out2<<<NODE_BLKS, 256>>>(b2, out);
}

// round 16
// speedup vs baseline: 1.5211x; 1.5211x over previous
#include <cuda_runtime.h>
#include <cuda_bf16.h>
#include <cstdint>

#define N_NODES 100000
#define N_EDGES 1600000
#define IN_CH   768
#define HID_CH  256
#define OUT_CH  2

#define SCAN_B 1024
#define N_SCAN_BLKS ((N_NODES + SCAN_B - 1) / SCAN_B)   // 98

// ---- scratch (device globals; allocation is forbidden) ----
__device__ __align__(16) float g_xw[(size_t)N_NODES * HID_CH]; // x @ W1
__device__ float g_deg [N_NODES];
__device__ float g_dinv[N_NODES];
__device__ __align__(8) float g_hw[(size_t)N_NODES * OUT_CH];  // relu(h) @ W2
__device__ int   g_cnt[N_NODES];
__device__ int   g_off[N_NODES];
__device__ int   g_cursor[N_NODES];
__device__ int   g_bsum[N_SCAN_BLKS];
__device__ int   g_csr_src[N_EDGES];
__device__ float g_csr_nrm[N_EDGES];
__device__ int   g_is64;
// W1 split to bf16 hi/lo, SAME [K][N] layout as input (for cp.async B tiles)
__device__ __align__(16) __nv_bfloat16 g_w1h[(size_t)IN_CH * HID_CH];
__device__ __align__(16) __nv_bfloat16 g_w1l[(size_t)IN_CH * HID_CH];

#define INIT_BLKS  ((N_NODES + 255) / 256)             // 391
#define SPLIT_BLKS ((IN_CH * HID_CH + 255) / 256)      // 768
#define SETUP_BLKS (INIT_BLKS + SPLIT_BLKS + 1)

// ---- fused setup: init deg/cnt, split W1, detect edge dtype ----
__global__ void k_setup(const float* __restrict__ W1,
                        const unsigned long long* __restrict__ ei) {
    int b = blockIdx.x;
    int tid = threadIdx.x;
    if (b < INIT_BLKS) {
        int i = b * 256 + tid;
        if (i < N_NODES) { g_deg[i] = 1.0f; g_cnt[i] = 0; }
    } else if (b < INIT_BLKS + SPLIT_BLKS) {
        int idx = (b - INIT_BLKS) * 256 + tid;
        if (idx < IN_CH * HID_CH) {
            float v = W1[idx];
            __nv_bfloat16 h = __float2bfloat16(v);
            __nv_bfloat16 l = __float2bfloat16(v - __bfloat162float(h));
            g_w1h[idx] = h;
            g_w1l[idx] = l;
        }
    } else {
        if (tid < 32) {
            bool hi = false;
            for (int i = tid; i < 1024; i += 32)
                hi |= (ei[i] >> 32) != 0ull;
            unsigned m = __ballot_sync(0xffffffffu, hi);
            if (tid == 0) g_is64 = (m == 0u);
        }
    }
}

__device__ __forceinline__ void load_edge(const void* ei_raw, int e, int& s, int& d) {
    if (g_is64) {
        const long long* ei = (const long long*)ei_raw;
        s = (int)ei[e];
        d = (int)ei[N_EDGES + e];
    } else {
        const int* ei = (const int*)ei_raw;
        s = ei[e];
        d = ei[N_EDGES + e];
    }
    if ((unsigned)s >= N_NODES) s = 0;
    if ((unsigned)d >= N_NODES) d = 0;
}

__global__ void k_prep(const void* __restrict__ ei_raw, const float* __restrict__ ew) {
    int e = blockIdx.x * blockDim.x + threadIdx.x;
    if (e >= N_EDGES) return;
    int s, d;
    load_edge(ei_raw, e, s, d);
    atomicAdd(&g_deg[d], ew[e]);
    atomicAdd(&g_cnt[d], 1);
}

// ---- scan1 with fused dinv (deg is final after k_prep) ----
__global__ void k_scan1() {
    __shared__ int s[SCAN_B];
    int tid = threadIdx.x;
    int i = blockIdx.x * SCAN_B + tid;
    if (i < N_NODES) {
        float dg = g_deg[i];
        g_dinv[i] = dg > 0.f ? rsqrtf(dg) : 0.f;
    }
    int v = (i < N_NODES) ? g_cnt[i] : 0;
    s[tid] = v;
    __syncthreads();
    #pragma unroll
    for (int d = 1; d < SCAN_B; d <<= 1) {
        int t = (tid >= d) ? s[tid - d] : 0;
        __syncthreads();
        s[tid] += t;
        __syncthreads();
    }
    if (i < N_NODES) g_off[i] = s[tid] - v;
    if (tid == SCAN_B - 1) g_bsum[blockIdx.x] = s[tid];
}

__global__ void k_scan2() {
    __shared__ int s[128];
    int tid = threadIdx.x;
    int v = (tid < N_SCAN_BLKS) ? g_bsum[tid] : 0;
    s[tid] = v;
    __syncthreads();
    #pragma unroll
    for (int d = 1; d < 128; d <<= 1) {
        int t = (tid >= d) ? s[tid - d] : 0;
        __syncthreads();
        s[tid] += t;
        __syncthreads();
    }
    if (tid < N_SCAN_BLKS) g_bsum[tid] = s[tid] - v;
}

__global__ void k_scan3() {
    int i = blockIdx.x * blockDim.x + threadIdx.x;
    if (i < N_NODES) {
        int o = g_off[i] + g_bsum[i / SCAN_B];
        g_off[i] = o;
        g_cursor[i] = o;
    }
}

__global__ void k_scatter(const void* __restrict__ ei_raw, const float* __restrict__ ew) {
    int e = blockIdx.x * blockDim.x + threadIdx.x;
    if (e >= N_EDGES) return;
    int s, d;
    load_edge(ei_raw, e, s, d);
    int pos = atomicAdd(&g_cursor[d], 1);
    if ((unsigned)pos >= N_EDGES) return;
    g_csr_src[pos] = s;
    g_csr_nrm[pos] = g_dinv[s] * ew[e] * g_dinv[d];
}

// == HMMA GEMM1 bf16-split 3-pass: BM=64 x BN=256, 256 thr, 2 CTAs/SM ======
__device__ __forceinline__ uint32_t smem_u32(const void* p) {
    return (uint32_t)__cvta_generic_to_shared(p);
}
__device__ __forceinline__ void ldsm_x4(uint32_t* r, uint32_t addr) {
    asm volatile("ldmatrix.sync.aligned.m8n8.x4.shared.b16 {%0,%1,%2,%3}, [%4];"
        : "=r"(r[0]), "=r"(r[1]), "=r"(r[2]), "=r"(r[3]) : "r"(addr));
}
__device__ __forceinline__ void ldsm_x4t(uint32_t* r, uint32_t addr) {
    asm volatile("ldmatrix.sync.aligned.m8n8.x4.trans.shared.b16 {%0,%1,%2,%3}, [%4];"
        : "=r"(r[0]), "=r"(r[1]), "=r"(r[2]), "=r"(r[3]) : "r"(addr));
}
__device__ __forceinline__ void mma_bf16(float* c, const uint32_t* a, const uint32_t* b) {
    asm volatile("mma.sync.aligned.m16n8k16.row.col.f32.bf16.bf16.f32 "
        "{%0,%1,%2,%3}, {%4,%5,%6,%7}, {%8,%9}, {%0,%1,%2,%3};"
        : "+f"(c[0]), "+f"(c[1]), "+f"(c[2]), "+f"(c[3])
        : "r"(a[0]), "r"(a[1]), "r"(a[2]), "r"(a[3]), "r"(b[0]), "r"(b[1]));
}
__device__ __forceinline__ uint32_t pack_split(float a, float b, uint32_t& lo) {
    __nv_bfloat16 ha = __float2bfloat16(a);
    __nv_bfloat16 hb = __float2bfloat16(b);
    __nv_bfloat16 la = __float2bfloat16(a - __bfloat162float(ha));
    __nv_bfloat16 lb = __float2bfloat16(b - __bfloat162float(hb));
    __nv_bfloat162 l2(la, lb); lo = *(uint32_t*)&l2;
    __nv_bfloat162 h2(ha, hb); return *(uint32_t*)&h2;
}
#define CP_ASYNC16(dst, src) \
    asm volatile("cp.async.ca.shared.global [%0], [%1], 16;" :: "r"(dst), "l"(src))
#define CP_COMMIT() asm volatile("cp.async.commit_group;" ::: "memory")
#define CP_WAIT0()  asm volatile("cp.async.wait_group 0;" ::: "memory")

#define BM 64
#define BN 256
#define BK 32
#define A_PITCH 40
#define B_PITCH 264
#define A_ST (BM * A_PITCH)   // 2560 halves
#define B_ST (BK * B_PITCH)   // 8448 halves
#define GEMM_SMEM_BYTES ((4 * A_ST + 4 * B_ST) * 2)   // 88064

__global__ __launch_bounds__(256, 2)
void k_gemm1_tc(const float* __restrict__ A) {
    extern __shared__ __align__(16) __nv_bfloat16 sm[];
    __nv_bfloat16* AH = sm;                 // [2][BM][A_PITCH]
    __nv_bfloat16* AL = AH + 2 * A_ST;
    __nv_bfloat16* BH = AL + 2 * A_ST;      // [2][BK][B_PITCH]
    __nv_bfloat16* BL = BH + 2 * B_ST;

    const int tid  = threadIdx.x;
    const int lane = tid & 31;
    const int wid  = tid >> 5;
    const int warp_m = wid & 1;             // 2 groups x 32 rows
    const int warp_n = wid >> 1;            // 4 groups x 64 cols
    const int m0 = blockIdx.x * BM;

    const int ar = tid >> 2;                // 0..63
    const int ac = (tid & 3) * 8;           // 0,8,16,24
    const bool a_ok = (m0 + ar) < N_NODES;

    float4 ra[2];
    #define LOAD_A(k0)                                                           \
        do {                                                                     \
            if (a_ok) {                                                          \
                const float* ap = A + (size_t)(m0 + ar) * IN_CH + (k0) + ac;     \
                ra[0] = *(const float4*)(ap);                                    \
                ra[1] = *(const float4*)(ap + 4);                                \
            } else {                                                             \
                ra[0] = ra[1] = make_float4(0.f, 0.f, 0.f, 0.f);                 \
            }                                                                    \
        } while (0)

    #define STS_A(st)                                                            \
        do {                                                                     \
            uint32_t h0, h1, h2, h3, l0, l1, l2, l3;                             \
            h0 = pack_split(ra[0].x, ra[0].y, l0);                               \
            h1 = pack_split(ra[0].z, ra[0].w, l1);                               \
            h2 = pack_split(ra[1].x, ra[1].y, l2);                               \
            h3 = pack_split(ra[1].z, ra[1].w, l3);                               \
            uint32_t off = ar * A_PITCH + ac;                                    \
            *(uint4*)(AH + (st) * A_ST + off) = make_uint4(h0, h1, h2, h3);      \
            *(uint4*)(AL + (st) * A_ST + off) = make_uint4(l0, l1, l2, l3);      \
        } while (0)

    // B: 32 rows x 32 segs (8 halves each) = 1024 segs per buffer; 256 thr x4
    #define CP_B(k0, st)                                                         \
        do {                                                                     \
            _Pragma("unroll")                                                    \
            for (int j = 0; j < 4; j++) {                                        \
                int u = tid + j * 256;                                           \
                int rw = u >> 5, sg = (u & 31) * 8;                              \
                uint32_t doff = ((st) * B_ST + rw * B_PITCH + sg) * 2;           \
                const __nv_bfloat16* sh = g_w1h + (size_t)((k0) + rw) * HID_CH + sg; \
                const __nv_bfloat16* sl = g_w1l + (size_t)((k0) + rw) * HID_CH + sg; \
                CP_ASYNC16(smem_u32(BH) + doff, sh);                             \
                CP_ASYNC16(smem_u32(BL) + doff, sl);                             \
            }                                                                    \
        } while (0)

    float acc[2][8][4];
    #pragma unroll
    for (int mi = 0; mi < 2; mi++)
        #pragma unroll
        for (int ni = 0; ni < 8; ni++)
            #pragma unroll
            for (int q = 0; q < 4; q++) acc[mi][ni][q] = 0.f;

    LOAD_A(0);
    CP_B(0, 0);
    CP_COMMIT();
    STS_A(0);
    CP_WAIT0();
    __syncthreads();

    const int bg   = lane >> 3;
    const int brow = ((bg & 1) << 3) + (lane & 7);
    const int bcol = (bg >> 1) << 3;

    int stage = 0;
    for (int k0 = 0; k0 < IN_CH; k0 += BK) {
        const bool has_next = (k0 + BK) < IN_CH;
        if (has_next) {
            LOAD_A(k0 + BK);
            CP_B(k0 + BK, stage ^ 1);
            CP_COMMIT();
        }

        const __nv_bfloat16* AHs = AH + stage * A_ST;
        const __nv_bfloat16* ALs = AL + stage * A_ST;
        const __nv_bfloat16* BHs = BH + stage * B_ST;
        const __nv_bfloat16* BLs = BL + stage * B_ST;

        #pragma unroll
        for (int ks = 0; ks < 2; ks++) {
            const int kk = ks * 16;
            uint32_t ah[2][4], al[2][4];
            {
                int row = warp_m * 32 + (lane & 15);
                int col = kk + ((lane >> 4) << 3);
                #pragma unroll
                for (int mi = 0; mi < 2; mi++) {
                    ldsm_x4(ah[mi], smem_u32(AHs + (row + mi * 16) * A_PITCH + col));
                    ldsm_x4(al[mi], smem_u32(ALs + (row + mi * 16) * A_PITCH + col));
                }
            }
            #pragma unroll
            for (int ni = 0; ni < 8; ni += 2) {
                int n = warp_n * 64 + ni * 8 + bcol;
                uint32_t bh[4], bl[4];
                ldsm_x4t(bh, smem_u32(BHs + (kk + brow) * B_PITCH + n));
                ldsm_x4t(bl, smem_u32(BLs + (kk + brow) * B_PITCH + n));
                #pragma unroll
                for (int mi = 0; mi < 2; mi++) {
                    mma_bf16(acc[mi][ni],     ah[mi], bh);
                    mma_bf16(acc[mi][ni],     ah[mi], bl);
                    mma_bf16(acc[mi][ni],     al[mi], bh);
                    mma_bf16(acc[mi][ni + 1], ah[mi], bh + 2);
                    mma_bf16(acc[mi][ni + 1], ah[mi], bl + 2);
                    mma_bf16(acc[mi][ni + 1], al[mi], bh + 2);
                }
            }
        }
        if (has_next) {
            STS_A(stage ^ 1);
            CP_WAIT0();
        }
        __syncthreads();
        stage ^= 1;
    }

    #pragma unroll
    for (int mi = 0; mi < 2; mi++) {
        int r = m0 + warp_m * 32 + mi * 16 + (lane >> 2);
        int cb = warp_n * 64 + (lane & 3) * 2;
        #pragma unroll
        for (int ni = 0; ni < 8; ni++) {
            int c = cb + ni * 8;
            if (r < N_NODES)
                *(float2*)(g_xw + (size_t)r * HID_CH + c) =
                    make_float2(acc[mi][ni][0], acc[mi][ni][1]);
            if (r + 8 < N_NODES)
                *(float2*)(g_xw + (size_t)(r + 8) * HID_CH + c) =
                    make_float2(acc[mi][ni][2], acc[mi][ni][3]);
        }
    }
}

// ---- fused layer-1 aggregation + bias + ReLU + GEMM2 (256 -> 2) ----
// One warp per node, lane owns 8 contiguous channels (R9 structure).
__global__ __launch_bounds__(256)
void k_agg_fused(const float* __restrict__ b1, const float* __restrict__ W2) {
    __shared__ float sW2[HID_CH * OUT_CH];
    __shared__ float sb1[HID_CH];
    int tid = threadIdx.x;
    sW2[tid] = W2[tid];
    sW2[tid + 256] = W2[tid + 256];
    sb1[tid] = b1[tid];
    __syncthreads();

    int node = (blockIdx.x * blockDim.x + tid) >> 5;
    int lane = tid & 31;
    if (node >= N_NODES) return;

    float di = g_dinv[node];
    float self = di * di;
    const float4* nrow = (const float4*)(g_xw + (size_t)node * HID_CH) + lane * 2;
    float4 v0 = nrow[0], v1 = nrow[1];
    float4 acc0 = make_float4(self * v0.x, self * v0.y, self * v0.z, self * v0.w);
    float4 acc1 = make_float4(self * v1.x, self * v1.y, self * v1.z, self * v1.w);

    int begin = g_off[node];
    int end = begin + g_cnt[node];
    for (int j0 = begin; j0 < end; j0 += 32) {
        int m = end - j0; if (m > 32) m = 32;
        int   s_l = (lane < m) ? g_csr_src[j0 + lane] : 0;
        float w_l = (lane < m) ? g_csr_nrm[j0 + lane] : 0.f;
        for (int t = 0; t < m; t++) {
            int   s = __shfl_sync(0xffffffffu, s_l, t);
            float w = __shfl_sync(0xffffffffu, w_l, t);
            const float4* r = (const float4*)(g_xw + (size_t)s * HID_CH) + lane * 2;
            float4 u0 = __ldg(r);
            float4 u1 = __ldg(r + 1);
            acc0.x += w * u0.x; acc0.y += w * u0.y; acc0.z += w * u0.z; acc0.w += w * u0.w;
            acc1.x += w * u1.x; acc1.y += w * u1.y; acc1.z += w * u1.z; acc1.w += w * u1.w;
        }
    }

    int c = lane * 8;
    float h[8];
    h[0] = fmaxf(acc0.x + sb1[c + 0], 0.f);
    h[1] = fmaxf(acc0.y + sb1[c + 1], 0.f);
    h[2] = fmaxf(acc0.z + sb1[c + 2], 0.f);
    h[3] = fmaxf(acc0.w + sb1[c + 3], 0.f);
    h[4] = fmaxf(acc1.x + sb1[c + 4], 0.f);
    h[5] = fmaxf(acc1.y + sb1[c + 5], 0.f);
    h[6] = fmaxf(acc1.z + sb1[c + 6], 0.f);
    h[7] = fmaxf(acc1.w + sb1[c + 7], 0.f);
    float a0 = 0.f, a1 = 0.f;
    #pragma unroll
    for (int i = 0; i < 8; i++) {
        a0 += h[i] * sW2[(c + i) * 2];
        a1 += h[i] * sW2[(c + i) * 2 + 1];
    }
    #pragma unroll
    for (int off = 16; off > 0; off >>= 1) {
        a0 += __shfl_down_sync(0xffffffffu, a0, off);
        a1 += __shfl_down_sync(0xffffffffu, a1, off);
    }
    if (lane == 0) {
        g_hw[node * 2]     = a0;
        g_hw[node * 2 + 1] = a1;
    }
}

// ---- layer-2 aggregation via CSR ----
__global__ void k_out2(const float* __restrict__ b2, float* __restrict__ out) {
    int n = blockIdx.x * blockDim.x + threadIdx.x;
    if (n >= N_NODES) return;
    float di = g_dinv[n];
    float self = di * di;
    float a0 = g_hw[2 * n]     * self;
    float a1 = g_hw[2 * n + 1] * self;
    int begin = g_off[n];
    int end = begin + g_cnt[n];
    for (int j = begin; j < end; j++) {
        int   s = g_csr_src[j];
        float w = g_csr_nrm[j];
        a0 += w * g_hw[2 * s];
        a1 += w * g_hw[2 * s + 1];
    }
    out[2 * n]     = a0 + b2[0];
    out[2 * n + 1] = a1 + b2[1];
}

extern "C" void kernel_launch(void* const* d_in, const int* in_sizes, int n_in,
                              void* d_out, int out_size) {
    const float* x  = (const float*)d_in[0];
    const void*  ei = d_in[1];
    const float* ew = (const float*)d_in[2];
    const float* W1 = (const float*)d_in[3];
    const float* b1 = (const float*)d_in[4];
    const float* W2 = (const float*)d_in[5];
    const float* b2 = (const float*)d_in[6];
    float* out = (float*)d_out;

    const int NODE_BLKS = (N_NODES + 255) / 256;
    const int EDGE_BLKS = (N_EDGES + 255) / 256;

    cudaFuncSetAttribute(k_gemm1_tc,
                         cudaFuncAttributeMaxDynamicSharedMemorySize, GEMM_SMEM_BYTES);

    // Serial single stream.
    k_setup<<<SETUP_BLKS, 256>>>(W1, (const unsigned long long*)ei);

    k_gemm1_tc<<<(N_NODES + BM - 1) / BM, 256, GEMM_SMEM_BYTES>>>(x);

    k_prep<<<EDGE_BLKS, 256>>>(ei, ew);
    k_scan1<<<N_SCAN_BLKS, SCAN_B>>>();     // dinv fused here
    k_scan2<<<1, 128>>>();
    k_scan3<<<NODE_BLKS, 256>>>();
    k_scatter<<<EDGE_BLKS, 256>>>(ei, ew);

    k_agg_fused<<<(N_NODES * 32 + 255) / 256, 256>>>(b1, W2);

    k_out2<<<NODE_BLKS, 256>>>(b2, out);
}

// round 17
// speedup vs baseline: 1.5223x; 1.0008x over previous
#include <cuda_runtime.h>
#include <cuda_bf16.h>
#include <cstdint>

#define N_NODES 100000
#define N_EDGES 1600000
#define IN_CH   768
#define HID_CH  256
#define OUT_CH  2

#define SCAN_B 1024
#define N_SCAN_BLKS ((N_NODES + SCAN_B - 1) / SCAN_B)   // 98

// ---- scratch (device globals; allocation is forbidden) ----
__device__ __align__(16) float g_xw[(size_t)N_NODES * HID_CH]; // x @ W1
__device__ float g_deg [N_NODES];
__device__ float g_dinv[N_NODES];
__device__ __align__(8) float g_hw[(size_t)N_NODES * OUT_CH];  // relu(h) @ W2
__device__ int   g_cnt[N_NODES];
__device__ int   g_off[N_NODES];
__device__ int   g_cursor[N_NODES];
__device__ unsigned g_pub[N_SCAN_BLKS];   // block totals: value | 0x80000000
__device__ int   g_csr_src[N_EDGES];
__device__ float g_csr_nrm[N_EDGES];
__device__ int   g_is64;
// W1 split to bf16 hi/lo, SAME [K][N] layout as input (for cp.async B tiles)
__device__ __align__(16) __nv_bfloat16 g_w1h[(size_t)IN_CH * HID_CH];
__device__ __align__(16) __nv_bfloat16 g_w1l[(size_t)IN_CH * HID_CH];

#define INIT_BLKS  ((N_NODES + 255) / 256)             // 391
#define SPLIT_BLKS ((IN_CH * HID_CH + 255) / 256)      // 768
#define SETUP_BLKS (INIT_BLKS + SPLIT_BLKS + 1)

// ---- fused setup: init deg/cnt/pub, split W1, detect edge dtype ----
__global__ void k_setup(const float* __restrict__ W1,
                        const unsigned long long* __restrict__ ei) {
    int b = blockIdx.x;
    int tid = threadIdx.x;
    if (b < INIT_BLKS) {
        int i = b * 256 + tid;
        if (i < N_NODES) { g_deg[i] = 1.0f; g_cnt[i] = 0; }
    } else if (b < INIT_BLKS + SPLIT_BLKS) {
        int idx = (b - INIT_BLKS) * 256 + tid;
        if (idx < IN_CH * HID_CH) {
            float v = W1[idx];
            __nv_bfloat16 h = __float2bfloat16(v);
            __nv_bfloat16 l = __float2bfloat16(v - __bfloat162float(h));
            g_w1h[idx] = h;
            g_w1l[idx] = l;
        }
    } else {
        if (tid < N_SCAN_BLKS) g_pub[tid] = 0u;
        if (tid < 32) {
            bool hi = false;
            for (int i = tid; i < 1024; i += 32)
                hi |= (ei[i] >> 32) != 0ull;
            unsigned m = __ballot_sync(0xffffffffu, hi);
            if (tid == 0) g_is64 = (m == 0u);
        }
    }
}

__device__ __forceinline__ void load_edge(const void* ei_raw, int e, int& s, int& d) {
    if (g_is64) {
        const long long* ei = (const long long*)ei_raw;
        s = (int)ei[e];
        d = (int)ei[N_EDGES + e];
    } else {
        const int* ei = (const int*)ei_raw;
        s = ei[e];
        d = ei[N_EDGES + e];
    }
    if ((unsigned)s >= N_NODES) s = 0;
    if ((unsigned)d >= N_NODES) d = 0;
}

__global__ void k_prep(const void* __restrict__ ei_raw, const float* __restrict__ ew) {
    int e = blockIdx.x * blockDim.x + threadIdx.x;
    if (e >= N_EDGES) return;
    int s, d;
    load_edge(ei_raw, e, s, d);
    atomicAdd(&g_deg[d], ew[e]);
    atomicAdd(&g_cnt[d], 1);
}

// ---- single-kernel scan (dinv + block scan + publish/lookback) ----
// 98 blocks <= SM count: all co-resident, lookback cannot deadlock.
__global__ void k_scanf() {
    __shared__ int s[SCAN_B];
    __shared__ int s_prefix;
    const int tid = threadIdx.x;
    const int b = blockIdx.x;
    const int i = b * SCAN_B + tid;

    if (i < N_NODES) {
        float dg = g_deg[i];
        g_dinv[i] = dg > 0.f ? rsqrtf(dg) : 0.f;
    }
    int v = (i < N_NODES) ? g_cnt[i] : 0;
    s[tid] = v;
    __syncthreads();
    #pragma unroll
    for (int d = 1; d < SCAN_B; d <<= 1) {
        int t = (tid >= d) ? s[tid - d] : 0;
        __syncthreads();
        s[tid] += t;
        __syncthreads();
    }
    int incl = s[tid];

    // publish this block's total (value and flag share one 32-bit word)
    if (tid == 0) {
        unsigned total = (unsigned)s[SCAN_B - 1];
        *(volatile unsigned*)&g_pub[b] = total | 0x80000000u;
    }

    // lookback: warp 0 sums all predecessor totals in parallel
    if (tid < 32) {
        int sum = 0;
        for (int t = tid; t < b; t += 32) {
            unsigned p;
            do { p = *(volatile unsigned*)&g_pub[t]; } while (!(p & 0x80000000u));
            sum += (int)(p & 0x7fffffffu);
        }
        #pragma unroll
        for (int off = 16; off > 0; off >>= 1)
            sum += __shfl_down_sync(0xffffffffu, sum, off);
        if (tid == 0) s_prefix = sum;
    }
    __syncthreads();

    if (i < N_NODES) {
        int o = incl - v + s_prefix;
        g_off[i] = o;
        g_cursor[i] = o;
    }
}

__global__ void k_scatter(const void* __restrict__ ei_raw, const float* __restrict__ ew) {
    int e = blockIdx.x * blockDim.x + threadIdx.x;
    if (e >= N_EDGES) return;
    int s, d;
    load_edge(ei_raw, e, s, d);
    int pos = atomicAdd(&g_cursor[d], 1);
    if ((unsigned)pos >= N_EDGES) return;
    g_csr_src[pos] = s;
    g_csr_nrm[pos] = g_dinv[s] * ew[e] * g_dinv[d];
}

// == HMMA GEMM1 bf16-split 3-pass: BM=64 x BN=256, 256 thr, 2 CTAs/SM ======
__device__ __forceinline__ uint32_t smem_u32(const void* p) {
    return (uint32_t)__cvta_generic_to_shared(p);
}
__device__ __forceinline__ void ldsm_x4(uint32_t* r, uint32_t addr) {
    asm volatile("ldmatrix.sync.aligned.m8n8.x4.shared.b16 {%0,%1,%2,%3}, [%4];"
        : "=r"(r[0]), "=r"(r[1]), "=r"(r[2]), "=r"(r[3]) : "r"(addr));
}
__device__ __forceinline__ void ldsm_x4t(uint32_t* r, uint32_t addr) {
    asm volatile("ldmatrix.sync.aligned.m8n8.x4.trans.shared.b16 {%0,%1,%2,%3}, [%4];"
        : "=r"(r[0]), "=r"(r[1]), "=r"(r[2]), "=r"(r[3]) : "r"(addr));
}
__device__ __forceinline__ void mma_bf16(float* c, const uint32_t* a, const uint32_t* b) {
    asm volatile("mma.sync.aligned.m16n8k16.row.col.f32.bf16.bf16.f32 "
        "{%0,%1,%2,%3}, {%4,%5,%6,%7}, {%8,%9}, {%0,%1,%2,%3};"
        : "+f"(c[0]), "+f"(c[1]), "+f"(c[2]), "+f"(c[3])
        : "r"(a[0]), "r"(a[1]), "r"(a[2]), "r"(a[3]), "r"(b[0]), "r"(b[1]));
}
__device__ __forceinline__ uint32_t pack_split(float a, float b, uint32_t& lo) {
    __nv_bfloat16 ha = __float2bfloat16(a);
    __nv_bfloat16 hb = __float2bfloat16(b);
    __nv_bfloat16 la = __float2bfloat16(a - __bfloat162float(ha));
    __nv_bfloat16 lb = __float2bfloat16(b - __bfloat162float(hb));
    __nv_bfloat162 l2(la, lb); lo = *(uint32_t*)&l2;
    __nv_bfloat162 h2(ha, hb); return *(uint32_t*)&h2;
}
#define CP_ASYNC16(dst, src) \
    asm volatile("cp.async.ca.shared.global [%0], [%1], 16;" :: "r"(dst), "l"(src))
#define CP_COMMIT() asm volatile("cp.async.commit_group;" ::: "memory")
#define CP_WAIT0()  asm volatile("cp.async.wait_group 0;" ::: "memory")

#define BM 64
#define BN 256
#define BK 32
#define A_PITCH 40
#define B_PITCH 264
#define A_ST (BM * A_PITCH)   // 2560 halves
#define B_ST (BK * B_PITCH)   // 8448 halves
#define GEMM_SMEM_BYTES ((4 * A_ST + 4 * B_ST) * 2)   // 88064

__global__ __launch_bounds__(256, 2)
void k_gemm1_tc(const float* __restrict__ A) {
    extern __shared__ __align__(16) __nv_bfloat16 sm[];
    __nv_bfloat16* AH = sm;                 // [2][BM][A_PITCH]
    __nv_bfloat16* AL = AH + 2 * A_ST;
    __nv_bfloat16* BH = AL + 2 * A_ST;      // [2][BK][B_PITCH]
    __nv_bfloat16* BL = BH + 2 * B_ST;

    const int tid  = threadIdx.x;
    const int lane = tid & 31;
    const int wid  = tid >> 5;
    const int warp_m = wid & 1;             // 2 groups x 32 rows
    const int warp_n = wid >> 1;            // 4 groups x 64 cols
    const int m0 = blockIdx.x * BM;

    const int ar = tid >> 2;                // 0..63
    const int ac = (tid & 3) * 8;           // 0,8,16,24
    const bool a_ok = (m0 + ar) < N_NODES;

    float4 ra[2];
    #define LOAD_A(k0)                                                           \
        do {                                                                     \
            if (a_ok) {                                                          \
                const float* ap = A + (size_t)(m0 + ar) * IN_CH + (k0) + ac;     \
                ra[0] = *(const float4*)(ap);                                    \
                ra[1] = *(const float4*)(ap + 4);                                \
            } else {                                                             \
                ra[0] = ra[1] = make_float4(0.f, 0.f, 0.f, 0.f);                 \
            }                                                                    \
        } while (0)

    #define STS_A(st)                                                            \
        do {                                                                     \
            uint32_t h0, h1, h2, h3, l0, l1, l2, l3;                             \
            h0 = pack_split(ra[0].x, ra[0].y, l0);                               \
            h1 = pack_split(ra[0].z, ra[0].w, l1);                               \
            h2 = pack_split(ra[1].x, ra[1].y, l2);                               \
            h3 = pack_split(ra[1].z, ra[1].w, l3);                               \
            uint32_t off = ar * A_PITCH + ac;                                    \
            *(uint4*)(AH + (st) * A_ST + off) = make_uint4(h0, h1, h2, h3);      \
            *(uint4*)(AL + (st) * A_ST + off) = make_uint4(l0, l1, l2, l3);      \
        } while (0)

    // B: 32 rows x 32 segs (8 halves each) = 1024 segs per buffer; 256 thr x4
    #define CP_B(k0, st)                                                         \
        do {                                                                     \
            _Pragma("unroll")                                                    \
            for (int j = 0; j < 4; j++) {                                        \
                int u = tid + j * 256;                                           \
                int rw = u >> 5, sg = (u & 31) * 8;                              \
                uint32_t doff = ((st) * B_ST + rw * B_PITCH + sg) * 2;           \
                const __nv_bfloat16* sh = g_w1h + (size_t)((k0) + rw) * HID_CH + sg; \
                const __nv_bfloat16* sl = g_w1l + (size_t)((k0) + rw) * HID_CH + sg; \
                CP_ASYNC16(smem_u32(BH) + doff, sh);                             \
                CP_ASYNC16(smem_u32(BL) + doff, sl);                             \
            }                                                                    \
        } while (0)

    float acc[2][8][4];
    #pragma unroll
    for (int mi = 0; mi < 2; mi++)
        #pragma unroll
        for (int ni = 0; ni < 8; ni++)
            #pragma unroll
            for (int q = 0; q < 4; q++) acc[mi][ni][q] = 0.f;

    LOAD_A(0);
    CP_B(0, 0);
    CP_COMMIT();
    STS_A(0);
    CP_WAIT0();
    __syncthreads();

    const int bg   = lane >> 3;
    const int brow = ((bg & 1) << 3) + (lane & 7);
    const int bcol = (bg >> 1) << 3;

    int stage = 0;
    for (int k0 = 0; k0 < IN_CH; k0 += BK) {
        const bool has_next = (k0 + BK) < IN_CH;
        if (has_next) {
            LOAD_A(k0 + BK);
            CP_B(k0 + BK, stage ^ 1);
            CP_COMMIT();
        }

        const __nv_bfloat16* AHs = AH + stage * A_ST;
        const __nv_bfloat16* ALs = AL + stage * A_ST;
        const __nv_bfloat16* BHs = BH + stage * B_ST;
        const __nv_bfloat16* BLs = BL + stage * B_ST;

        #pragma unroll
        for (int ks = 0; ks < 2; ks++) {
            const int kk = ks * 16;
            uint32_t ah[2][4], al[2][4];
            {
                int row = warp_m * 32 + (lane & 15);
                int col = kk + ((lane >> 4) << 3);
                #pragma unroll
                for (int mi = 0; mi < 2; mi++) {
                    ldsm_x4(ah[mi], smem_u32(AHs + (row + mi * 16) * A_PITCH + col));
                    ldsm_x4(al[mi], smem_u32(ALs + (row + mi * 16) * A_PITCH + col));
                }
            }
            #pragma unroll
            for (int ni = 0; ni < 8; ni += 2) {
                int n = warp_n * 64 + ni * 8 + bcol;
                uint32_t bh[4], bl[4];
                ldsm_x4t(bh, smem_u32(BHs + (kk + brow) * B_PITCH + n));
                ldsm_x4t(bl, smem_u32(BLs + (kk + brow) * B_PITCH + n));
                #pragma unroll
                for (int mi = 0; mi < 2; mi++) {
                    mma_bf16(acc[mi][ni],     ah[mi], bh);
                    mma_bf16(acc[mi][ni],     ah[mi], bl);
                    mma_bf16(acc[mi][ni],     al[mi], bh);
                    mma_bf16(acc[mi][ni + 1], ah[mi], bh + 2);
                    mma_bf16(acc[mi][ni + 1], ah[mi], bl + 2);
                    mma_bf16(acc[mi][ni + 1], al[mi], bh + 2);
                }
            }
        }
        if (has_next) {
            STS_A(stage ^ 1);
            CP_WAIT0();
        }
        __syncthreads();
        stage ^= 1;
    }

    #pragma unroll
    for (int mi = 0; mi < 2; mi++) {
        int r = m0 + warp_m * 32 + mi * 16 + (lane >> 2);
        int cb = warp_n * 64 + (lane & 3) * 2;
        #pragma unroll
        for (int ni = 0; ni < 8; ni++) {
            int c = cb + ni * 8;
            if (r < N_NODES)
                *(float2*)(g_xw + (size_t)r * HID_CH + c) =
                    make_float2(acc[mi][ni][0], acc[mi][ni][1]);
            if (r + 8 < N_NODES)
                *(float2*)(g_xw + (size_t)(r + 8) * HID_CH + c) =
                    make_float2(acc[mi][ni][2], acc[mi][ni][3]);
        }
    }
}

// ---- fused layer-1 aggregation + bias + ReLU + GEMM2 (256 -> 2) ----
// One warp per node, lane owns 8 contiguous channels (R9 structure).
__global__ __launch_bounds__(256)
void k_agg_fused(const float* __restrict__ b1, const float* __restrict__ W2) {
    __shared__ float sW2[HID_CH * OUT_CH];
    __shared__ float sb1[HID_CH];
    int tid = threadIdx.x;
    sW2[tid] = W2[tid];
    sW2[tid + 256] = W2[tid + 256];
    sb1[tid] = b1[tid];
    __syncthreads();

    int node = (blockIdx.x * blockDim.x + tid) >> 5;
    int lane = tid & 31;
    if (node >= N_NODES) return;

    float di = g_dinv[node];
    float self = di * di;
    const float4* nrow = (const float4*)(g_xw + (size_t)node * HID_CH) + lane * 2;
    float4 v0 = nrow[0], v1 = nrow[1];
    float4 acc0 = make_float4(self * v0.x, self * v0.y, self * v0.z, self * v0.w);
    float4 acc1 = make_float4(self * v1.x, self * v1.y, self * v1.z, self * v1.w);

    int begin = g_off[node];
    int end = begin + g_cnt[node];
    for (int j0 = begin; j0 < end; j0 += 32) {
        int m = end - j0; if (m > 32) m = 32;
        int   s_l = (lane < m) ? g_csr_src[j0 + lane] : 0;
        float w_l = (lane < m) ? g_csr_nrm[j0 + lane] : 0.f;
        for (int t = 0; t < m; t++) {
            int   s = __shfl_sync(0xffffffffu, s_l, t);
            float w = __shfl_sync(0xffffffffu, w_l, t);
            const float4* r = (const float4*)(g_xw + (size_t)s * HID_CH) + lane * 2;
            float4 u0 = __ldg(r);
            float4 u1 = __ldg(r + 1);
            acc0.x += w * u0.x; acc0.y += w * u0.y; acc0.z += w * u0.z; acc0.w += w * u0.w;
            acc1.x += w * u1.x; acc1.y += w * u1.y; acc1.z += w * u1.z; acc1.w += w * u1.w;
        }
    }

    int c = lane * 8;
    float h[8];
    h[0] = fmaxf(acc0.x + sb1[c + 0], 0.f);
    h[1] = fmaxf(acc0.y + sb1[c + 1], 0.f);
    h[2] = fmaxf(acc0.z + sb1[c + 2], 0.f);
    h[3] = fmaxf(acc0.w + sb1[c + 3], 0.f);
    h[4] = fmaxf(acc1.x + sb1[c + 4], 0.f);
    h[5] = fmaxf(acc1.y + sb1[c + 5], 0.f);
    h[6] = fmaxf(acc1.z + sb1[c + 6], 0.f);
    h[7] = fmaxf(acc1.w + sb1[c + 7], 0.f);
    float a0 = 0.f, a1 = 0.f;
    #pragma unroll
    for (int i = 0; i < 8; i++) {
        a0 += h[i] * sW2[(c + i) * 2];
        a1 += h[i] * sW2[(c + i) * 2 + 1];
    }
    #pragma unroll
    for (int off = 16; off > 0; off >>= 1) {
        a0 += __shfl_down_sync(0xffffffffu, a0, off);
        a1 += __shfl_down_sync(0xffffffffu, a1, off);
    }
    if (lane == 0) {
        g_hw[node * 2]     = a0;
        g_hw[node * 2 + 1] = a1;
    }
}

// ---- layer-2 aggregation via CSR ----
__global__ void k_out2(const float* __restrict__ b2, float* __restrict__ out) {
    int n = blockIdx.x * blockDim.x + threadIdx.x;
    if (n >= N_NODES) return;
    float di = g_dinv[n];
    float self = di * di;
    float a0 = g_hw[2 * n]     * self;
    float a1 = g_hw[2 * n + 1] * self;
    int begin = g_off[n];
    int end = begin + g_cnt[n];
    for (int j = begin; j < end; j++) {
        int   s = g_csr_src[j];
        float w = g_csr_nrm[j];
        a0 += w * g_hw[2 * s];
        a1 += w * g_hw[2 * s + 1];
    }
    out[2 * n]     = a0 + b2[0];
    out[2 * n + 1] = a1 + b2[1];
}

extern "C" void kernel_launch(void* const* d_in, const int* in_sizes, int n_in,
                              void* d_out, int out_size) {
    const float* x  = (const float*)d_in[0];
    const void*  ei = d_in[1];
    const float* ew = (const float*)d_in[2];
    const float* W1 = (const float*)d_in[3];
    const float* b1 = (const float*)d_in[4];
    const float* W2 = (const float*)d_in[5];
    const float* b2 = (const float*)d_in[6];
    float* out = (float*)d_out;

    const int NODE_BLKS = (N_NODES + 255) / 256;
    const int EDGE_BLKS = (N_EDGES + 255) / 256;

    cudaFuncSetAttribute(k_gemm1_tc,
                         cudaFuncAttributeMaxDynamicSharedMemorySize, GEMM_SMEM_BYTES);

    // Serial single stream.
    k_setup<<<SETUP_BLKS, 256>>>(W1, (const unsigned long long*)ei);

    k_gemm1_tc<<<(N_NODES + BM - 1) / BM, 256, GEMM_SMEM_BYTES>>>(x);

    k_prep<<<EDGE_BLKS, 256>>>(ei, ew);
    k_scanf<<<N_SCAN_BLKS, SCAN_B>>>();     // dinv + full scan in one kernel
    k_scatter<<<EDGE_BLKS, 256>>>(ei, ew);

    k_agg_fused<<<(N_NODES * 32 + 255) / 256, 256>>>(b1, W2);

    k_out2<<<NODE_BLKS, 256>>>(b2, out);
}